// round 14
// baseline (speedup 1.0000x reference)
#include <cuda_runtime.h>
#include <cuda_bf16.h>
#include <math.h>
#include <stdint.h>

#define B_ 4
#define T_ 1024
#define S_ 1024
#define E_ 1024
#define H_ 16
#define D_ 64
#define MAXLEN 2048

// ---------------- Pre-split bf16-pair device globals ----------------
__device__ uint32_t qa_hi[4096 * 512], qa_lo[4096 * 512];
__device__ uint32_t ka_hi[4096 * 512], ka_lo[4096 * 512];
__device__ uint32_t va_hi[4096 * 512], va_lo[4096 * 512];
__device__ uint32_t ao_hi[4096 * 512], ao_lo[4096 * 512];
__device__ uint32_t qw_hi[1024 * 512], qw_lo[1024 * 512];
__device__ uint32_t kw_hi[1024 * 512], kw_lo[1024 * 512];
__device__ uint32_t vw_hi[1024 * 512], vw_lo[1024 * 512];
__device__ uint32_t ow_hi[1024 * 512], ow_lo[1024 * 512];
// Projected q/k/v: [z][t][32] pair-words (pairs along d), z = b*16+h
__device__ uint32_t gq_hi[64 * 1024 * 32], gq_lo[64 * 1024 * 32];
__device__ uint32_t gk_hi[64 * 1024 * 32], gk_lo[64 * 1024 * 32];
__device__ uint32_t gv_hi[64 * 1024 * 32], gv_lo[64 * 1024 * 32];

__device__ __forceinline__ float neg_big() { return -1e30f; }

__device__ __forceinline__ void split2(float x, float y, uint32_t& hi, uint32_t& lo) {
    __nv_bfloat16 xh = __float2bfloat16(x);
    __nv_bfloat16 yh = __float2bfloat16(y);
    __nv_bfloat16 xl = __float2bfloat16(x - __bfloat162float(xh));
    __nv_bfloat16 yl = __float2bfloat16(y - __bfloat162float(yh));
    hi = (uint32_t)__bfloat16_as_ushort(xh) | ((uint32_t)__bfloat16_as_ushort(yh) << 16);
    lo = (uint32_t)__bfloat16_as_ushort(xl) | ((uint32_t)__bfloat16_as_ushort(yl) << 16);
}

__device__ __forceinline__ void mma_bf16(float c[4], const uint32_t a[4], const uint32_t b[2]) {
    asm volatile(
        "mma.sync.aligned.m16n8k16.row.col.f32.bf16.bf16.f32 "
        "{%0,%1,%2,%3}, {%4,%5,%6,%7}, {%8,%9}, {%0,%1,%2,%3};"
        : "+f"(c[0]), "+f"(c[1]), "+f"(c[2]), "+f"(c[3])
        : "r"(a[0]), "r"(a[1]), "r"(a[2]), "r"(a[3]), "r"(b[0]), "r"(b[1]));
}

__device__ __forceinline__ void ldmat_x4(uint32_t r[4], uint32_t addr) {
    asm volatile("ldmatrix.sync.aligned.m8n8.x4.shared.b16 {%0,%1,%2,%3}, [%4];"
                 : "=r"(r[0]), "=r"(r[1]), "=r"(r[2]), "=r"(r[3]) : "r"(addr));
}
__device__ __forceinline__ void ldmat_x2(uint32_t& r0, uint32_t& r1, uint32_t addr) {
    asm volatile("ldmatrix.sync.aligned.m8n8.x2.shared.b16 {%0,%1}, [%2];"
                 : "=r"(r0), "=r"(r1) : "r"(addr));
}
__device__ __forceinline__ void ldmat_x2_trans(uint32_t& r0, uint32_t& r1, uint32_t addr) {
    asm volatile("ldmatrix.sync.aligned.m8n8.x2.trans.shared.b16 {%0,%1}, [%2];"
                 : "=r"(r0), "=r"(r1) : "r"(addr));
}
__device__ __forceinline__ void cpa16(uint32_t dst, const void* src) {
    asm volatile("cp.async.cg.shared.global [%0], [%1], 16;" :: "r"(dst), "l"(src));
}
template <int N>
__device__ __forceinline__ void cpa_wait() {
    asm volatile("cp.async.wait_group %0;" :: "n"(N) : "memory");
}
__device__ __forceinline__ void cpa_commit() {
    asm volatile("cp.async.commit_group;" ::: "memory");
}

// ---------------------------------------------------------------------------
// Merged split kernel (R11)
// ---------------------------------------------------------------------------
#define NA4 (4096 * 1024 / 4)
#define NW4 (1024 * 1024 / 4)
__global__ __launch_bounds__(256) void split_all(
    const float4* __restrict__ q,  const float4* __restrict__ k,
    const float4* __restrict__ v,  const float4* __restrict__ qw,
    const float4* __restrict__ kw, const float4* __restrict__ vw,
    const float4* __restrict__ ow)
{
    int i0 = blockIdx.x * 1024;
    const float4* src;
    uint2 *hi, *lo;
    int li0 = i0;
    if (li0 < 3 * NA4) {
        int seg = li0 / NA4; li0 -= seg * NA4;
        src = (seg == 0) ? q : (seg == 1) ? k : v;
        hi = (uint2*)((seg == 0) ? qa_hi : (seg == 1) ? ka_hi : va_hi);
        lo = (uint2*)((seg == 0) ? qa_lo : (seg == 1) ? ka_lo : va_lo);
    } else {
        li0 -= 3 * NA4;
        int seg = li0 / NW4; li0 -= seg * NW4;
        src = (seg == 0) ? qw : (seg == 1) ? kw : (seg == 2) ? vw : ow;
        hi = (uint2*)((seg == 0) ? qw_hi : (seg == 1) ? kw_hi : (seg == 2) ? vw_hi : ow_hi);
        lo = (uint2*)((seg == 0) ? qw_lo : (seg == 1) ? kw_lo : (seg == 2) ? vw_lo : ow_lo);
    }
    float4 f[4];
#pragma unroll
    for (int c = 0; c < 4; c++) f[c] = src[li0 + threadIdx.x + c * 256];
#pragma unroll
    for (int c = 0; c < 4; c++) {
        int li = li0 + threadIdx.x + c * 256;
        uint32_t h0, l0, h1, l1;
        split2(f[c].x, f[c].y, h0, l0);
        split2(f[c].z, f[c].w, h1, l1);
        hi[li] = make_uint2(h0, h1);
        lo[li] = make_uint2(l0, l1);
    }
}

// ---------------------------------------------------------------------------
// GEMM mainloop. MMA phase reordered: per row-block i, three passes over j
// (hh, lh, hl) so same-accumulator MMAs are 4 apart (RAW chain broken).
// ---------------------------------------------------------------------------
#define GEMM_BODY(Ah, Al, Bh, Bl, K)                                              \
    const int lane = tid & 31, warp = tid >> 5;                                   \
    const int wy = warp >> 2, wx = warp & 3;                                      \
    const int grp = lane >> 2, tig = lane & 3;                                    \
    const int K2 = (K) >> 1;                                                      \
    uint32_t sbase;                                                               \
    asm("{.reg .u64 t; cvta.to.shared.u64 t, %1; cvt.u32.u64 %0, t;}"             \
        : "=r"(sbase) : "l"(dsm));                                                \
    float acc[4][4][4];                                                           \
    _Pragma("unroll")                                                             \
    for (int i = 0; i < 4; i++)                                                   \
        _Pragma("unroll")                                                         \
        for (int j = 0; j < 4; j++)                                               \
            _Pragma("unroll")                                                     \
            for (int r = 0; r < 4; r++) acc[i][j][r] = 0.0f;                      \
    const int nT = (K) / 32;                                                      \
    const uint32_t aA = (uint32_t)((wy * 64 + (lane & 15)) * 80 + (lane >> 4) * 16);       \
    const uint32_t aB = (uint32_t)(40960 + (wx * 32 + (lane & 7)) * 80 + ((lane >> 3) & 1) * 16); \
    {                                                                             \
        _Pragma("unroll")                                                         \
        for (int l = 0; l < 2; l++) {                                             \
            int idx = tid + l * 256;                                              \
            int row = idx >> 2, c4 = idx & 3;                                     \
            uint32_t off = (uint32_t)(row * 80 + c4 * 16);                        \
            size_t sA = (size_t)(m0 + row) * K2 + c4 * 4;                         \
            size_t sB = (size_t)(n0 + row) * K2 + c4 * 4;                         \
            cpa16(sbase + off,         (Ah) + sA);                                \
            cpa16(sbase + 20480 + off, (Al) + sA);                                \
            cpa16(sbase + 40960 + off, (Bh) + sB);                                \
            cpa16(sbase + 61440 + off, (Bl) + sB);                                \
        }                                                                         \
        cpa_commit();                                                             \
    }                                                                             \
    for (int t = 0; t < nT; t++) {                                                \
        const int st = t & 1;                                                     \
        if (t + 1 < nT) {                                                         \
            _Pragma("unroll")                                                     \
            for (int l = 0; l < 2; l++) {                                         \
                int idx = tid + l * 256;                                          \
                int row = idx >> 2, c4 = idx & 3;                                 \
                uint32_t off = (uint32_t)((st ^ 1) * 10240 + row * 80 + c4 * 16); \
                size_t sA = (size_t)(m0 + row) * K2 + (t + 1) * 16 + c4 * 4;      \
                size_t sB = (size_t)(n0 + row) * K2 + (t + 1) * 16 + c4 * 4;      \
                cpa16(sbase + off,         (Ah) + sA);                            \
                cpa16(sbase + 20480 + off, (Al) + sA);                            \
                cpa16(sbase + 40960 + off, (Bh) + sB);                            \
                cpa16(sbase + 61440 + off, (Bl) + sB);                            \
            }                                                                     \
            cpa_commit();                                                         \
            cpa_wait<1>();                                                        \
        } else {                                                                  \
            cpa_wait<0>();                                                        \
        }                                                                         \
        __syncthreads();                                                          \
        const uint32_t sb = sbase + st * 10240;                                   \
        _Pragma("unroll")                                                         \
        for (int ks = 0; ks < 2; ks++) {                                          \
            uint32_t bh[4][2], bl[4][2];                                          \
            _Pragma("unroll")                                                     \
            for (int j = 0; j < 4; j++) {                                         \
                ldmat_x2(bh[j][0], bh[j][1], sb + aB + j * 640 + ks * 32);        \
                ldmat_x2(bl[j][0], bl[j][1], sb + aB + 20480 + j * 640 + ks * 32);\
            }                                                                     \
            _Pragma("unroll")                                                     \
            for (int i = 0; i < 4; i++) {                                         \
                uint32_t ah[4], al[4];                                            \
                ldmat_x4(ah, sb + aA + i * 1280 + ks * 32);                       \
                ldmat_x4(al, sb + aA + 20480 + i * 1280 + ks * 32);               \
                _Pragma("unroll")                                                 \
                for (int j = 0; j < 4; j++) mma_bf16(acc[i][j], ah, bh[j]);       \
                _Pragma("unroll")                                                 \
                for (int j = 0; j < 4; j++) mma_bf16(acc[i][j], al, bh[j]);       \
                _Pragma("unroll")                                                 \
                for (int j = 0; j < 4; j++) mma_bf16(acc[i][j], ah, bl[j]);       \
            }                                                                     \
        }                                                                         \
        __syncthreads();                                                          \
    }

// ---------------------------------------------------------------------------
// Merged Q/K/V projection GEMM
// ---------------------------------------------------------------------------
__global__ __launch_bounds__(256, 2) void proj_qkv(
    const float* __restrict__ q_b, const float* __restrict__ k_b,
    const float* __restrict__ v_b, const float* __restrict__ rel)
{
    extern __shared__ uint32_t dsm[];
    const int which = blockIdx.z;
    const int tid = threadIdx.x;
    const int m0 = blockIdx.y * 128;
    const int n0 = blockIdx.x * 128;

    const uint32_t* Ah = (which == 0) ? qa_hi : (which == 1) ? ka_hi : va_hi;
    const uint32_t* Al = (which == 0) ? qa_lo : (which == 1) ? ka_lo : va_lo;
    const uint32_t* Bh = (which == 0) ? qw_hi : (which == 1) ? kw_hi : vw_hi;
    const uint32_t* Bl = (which == 0) ? qw_lo : (which == 1) ? kw_lo : vw_lo;
    const float* bias  = (which == 0) ? q_b : (which == 1) ? k_b : v_b;
    uint32_t* Dh = (which == 0) ? gq_hi : (which == 1) ? gk_hi : gv_hi;
    uint32_t* Dl = (which == 0) ? gq_lo : (which == 1) ? gk_lo : gv_lo;

    GEMM_BODY(Ah, Al, Bh, Bl, E_)

#pragma unroll
    for (int i = 0; i < 4; i++) {
        int mrow = m0 + wy * 64 + i * 16 + grp;
#pragma unroll
        for (int j = 0; j < 4; j++) {
            int ne = n0 + wx * 32 + j * 8 + 2 * tig;
            int h = ne >> 6, dl = ne & 63, dw = dl >> 1;
            float b0 = bias[ne], b1 = bias[ne + 1];
#pragma unroll
            for (int half = 0; half < 2; half++) {
                int m = mrow + half * 8;
                int bb = m >> 10, tt = m & 1023;
                float v0 = acc[i][j][2 * half]     + b0;
                float v1 = acc[i][j][2 * half + 1] + b1;
                if (which == 1) {
                    v0 += rel[((size_t)h * MAXLEN + tt) * D_ + dl];
                    v1 += rel[((size_t)h * MAXLEN + tt) * D_ + dl + 1];
                }
                uint32_t hw, lw;
                split2(v0, v1, hw, lw);
                size_t di = ((size_t)(bb * H_ + h) * T_ + tt) * 32 + dw;
                Dh[di] = hw;
                Dl[di] = lw;
            }
        }
    }
}

// ---------------------------------------------------------------------------
// O projection GEMM
// ---------------------------------------------------------------------------
__global__ __launch_bounds__(256, 2) void proj_o(
    const float* __restrict__ bias, float* __restrict__ out)
{
    extern __shared__ uint32_t dsm[];
    const int tid = threadIdx.x;
    const int m0 = blockIdx.y * 128;
    const int n0 = blockIdx.x * 128;

    GEMM_BODY(ao_hi, ao_lo, ow_hi, ow_lo, E_)

#pragma unroll
    for (int i = 0; i < 4; i++) {
        int mrow = m0 + wy * 64 + i * 16 + grp;
#pragma unroll
        for (int j = 0; j < 4; j++) {
            int ne = n0 + wx * 32 + j * 8 + 2 * tig;
            float b0 = bias[ne], b1 = bias[ne + 1];
            out[(size_t)mrow * E_ + ne]           = acc[i][j][0] + b0;
            out[(size_t)mrow * E_ + ne + 1]       = acc[i][j][1] + b1;
            out[(size_t)(mrow + 8) * E_ + ne]     = acc[i][j][2] + b0;
            out[(size_t)(mrow + 8) * E_ + ne + 1] = acc[i][j][3] + b1;
        }
    }
}

// ---------------------------------------------------------------------------
// Fused flash attention (R11 double-buffered), MMA phases reordered into
// grouped passes (4 accumulators per group, 3 passes).
// ---------------------------------------------------------------------------
__global__ __launch_bounds__(256, 2) void flash_attn(const unsigned char* __restrict__ mask)
{
    extern __shared__ uint32_t sm[];
    uint32_t* Qhi = sm;
    uint32_t* Qlo = sm + 4608;

    const int tid = threadIdx.x;
    const int lane = tid & 31, warp = tid >> 5;
    const int grp = lane >> 2, tig = lane & 3;
    const int m0 = blockIdx.x * 128;
    const int z  = blockIdx.y;
    const int bb = z >> 4, h = z & 15;

    const unsigned char* mrow_g = mask + (size_t)bb * S_;

    uint32_t sbase;
    asm("{.reg .u64 t; cvta.to.shared.u64 t, %1; cvt.u32.u64 %0, t;}"
        : "=r"(sbase) : "l"(sm));
    const uint32_t vrow0 = sbase + 55296 + (lane & 15) * 144;

#pragma unroll
    for (int l = 0; l < 4; l++) {
        int idx = tid + l * 256;
        int row = idx >> 3, c4 = idx & 7;
        uint32_t off = (uint32_t)(row * 144 + c4 * 16);
        size_t src = ((size_t)z * T_ + m0 + row) * 32 + c4 * 4;
        cpa16(sbase + off,         gq_hi + src);
        cpa16(sbase + 18432 + off, gq_lo + src);
    }

#define KVFILL(tt, sg)                                                            \
    {                                                                             \
        uint32_t sgo = (uint32_t)(sg) * 36864;                                    \
        _Pragma("unroll")                                                         \
        for (int l = 0; l < 2; l++) {                                             \
            int idx = tid + l * 256;                                              \
            int row = idx >> 3, c4 = idx & 7;                                     \
            uint32_t off = sgo + (uint32_t)(row * 144 + c4 * 16);                 \
            size_t src = ((size_t)z * S_ + (tt) * 64 + row) * 32 + c4 * 4;        \
            cpa16(sbase + 36864 + off, gk_hi + src);                              \
            cpa16(sbase + 46080 + off, gk_lo + src);                              \
            cpa16(sbase + 55296 + off, gv_hi + src);                              \
            cpa16(sbase + 64512 + off, gv_lo + src);                              \
        }                                                                         \
        cpa_commit();                                                             \
    }

    float accO[8][4];
#pragma unroll
    for (int jd = 0; jd < 8; jd++)
#pragma unroll
        for (int r = 0; r < 4; r++) accO[jd][r] = 0.0f;
    float m0r = -1e29f, m1r = -1e29f, l0r = 0.0f, l1r = 0.0f;

    const int r0 = warp * 16 + grp;

    KVFILL(0, 0);

    for (int t = 0; t < S_ / 64; t++) {
        const int st = t & 1;
        const int s0 = t * 64;
        if (t + 1 < S_ / 64) { KVFILL(t + 1, st ^ 1); cpa_wait<1>(); }
        else                 { cpa_wait<0>(); }
        __syncthreads();

        const uint32_t* KhiS = sm + 9216 + st * 9216;
        const uint32_t* KloS = sm + 11520 + st * 9216;
        const uint32_t vrow_h = vrow0 + st * 36864;

        float acc[8][4];
#pragma unroll
        for (int j = 0; j < 8; j++)
#pragma unroll
            for (int r = 0; r < 4; r++) acc[j][r] = 0.0f;

        // Scores: per ks, 2 groups of 4 columns; 3 passes per group.
#pragma unroll
        for (int ks = 0; ks < 4; ks++) {
            const int kb = ks * 8;
            uint32_t qh[4], ql[4];
            qh[0] = Qhi[r0 * 36 + kb + tig];
            qh[1] = Qhi[(r0 + 8) * 36 + kb + tig];
            qh[2] = Qhi[r0 * 36 + kb + tig + 4];
            qh[3] = Qhi[(r0 + 8) * 36 + kb + tig + 4];
            ql[0] = Qlo[r0 * 36 + kb + tig];
            ql[1] = Qlo[(r0 + 8) * 36 + kb + tig];
            ql[2] = Qlo[r0 * 36 + kb + tig + 4];
            ql[3] = Qlo[(r0 + 8) * 36 + kb + tig + 4];
#pragma unroll
            for (int g = 0; g < 2; g++) {
                uint32_t kh[4][2], kl[4][2];
#pragma unroll
                for (int jj = 0; jj < 4; jj++) {
                    int c0 = (g * 4 + jj) * 8 + grp;
                    kh[jj][0] = KhiS[c0 * 36 + kb + tig];
                    kh[jj][1] = KhiS[c0 * 36 + kb + tig + 4];
                    kl[jj][0] = KloS[c0 * 36 + kb + tig];
                    kl[jj][1] = KloS[c0 * 36 + kb + tig + 4];
                }
#pragma unroll
                for (int jj = 0; jj < 4; jj++) mma_bf16(acc[g * 4 + jj], qh, kh[jj]);
#pragma unroll
                for (int jj = 0; jj < 4; jj++) mma_bf16(acc[g * 4 + jj], ql, kh[jj]);
#pragma unroll
                for (int jj = 0; jj < 4; jj++) mma_bf16(acc[g * 4 + jj], qh, kl[jj]);
            }
        }

#pragma unroll
        for (int j = 0; j < 8; j++) {
            int c = s0 + j * 8 + 2 * tig;
            if (mrow_g[c])     { acc[j][0] = neg_big(); acc[j][2] = neg_big(); }
            if (mrow_g[c + 1]) { acc[j][1] = neg_big(); acc[j][3] = neg_big(); }
        }

        float tm0 = neg_big(), tm1 = neg_big();
#pragma unroll
        for (int j = 0; j < 8; j++) {
            tm0 = fmaxf(tm0, fmaxf(acc[j][0], acc[j][1]));
            tm1 = fmaxf(tm1, fmaxf(acc[j][2], acc[j][3]));
        }
        tm0 = fmaxf(tm0, __shfl_xor_sync(0xffffffffu, tm0, 1));
        tm0 = fmaxf(tm0, __shfl_xor_sync(0xffffffffu, tm0, 2));
        tm1 = fmaxf(tm1, __shfl_xor_sync(0xffffffffu, tm1, 1));
        tm1 = fmaxf(tm1, __shfl_xor_sync(0xffffffffu, tm1, 2));

        float mn0 = fmaxf(fmaxf(m0r, tm0), -1e29f);
        float mn1 = fmaxf(fmaxf(m1r, tm1), -1e29f);
        float sc0 = __expf(m0r - mn0);
        float sc1 = __expf(m1r - mn1);

        float ts0 = 0.0f, ts1 = 0.0f;
#pragma unroll
        for (int j = 0; j < 8; j++) {
            acc[j][0] = __expf(acc[j][0] - mn0);
            acc[j][1] = __expf(acc[j][1] - mn0);
            acc[j][2] = __expf(acc[j][2] - mn1);
            acc[j][3] = __expf(acc[j][3] - mn1);
            ts0 += acc[j][0] + acc[j][1];
            ts1 += acc[j][2] + acc[j][3];
        }
        ts0 += __shfl_xor_sync(0xffffffffu, ts0, 1);
        ts0 += __shfl_xor_sync(0xffffffffu, ts0, 2);
        ts1 += __shfl_xor_sync(0xffffffffu, ts1, 1);
        ts1 += __shfl_xor_sync(0xffffffffu, ts1, 2);

        l0r = l0r * sc0 + ts0;
        l1r = l1r * sc1 + ts1;
        m0r = mn0; m1r = mn1;

#pragma unroll
        for (int jd = 0; jd < 8; jd++) {
            accO[jd][0] *= sc0; accO[jd][1] *= sc0;
            accO[jd][2] *= sc1; accO[jd][3] *= sc1;
        }

        // PV: per ks, 2 groups of 4 d-columns; 3 passes per group.
#pragma unroll
        for (int ks = 0; ks < 4; ks++) {
            uint32_t ah[4], al[4];
            split2(acc[2 * ks][0],     acc[2 * ks][1],     ah[0], al[0]);
            split2(acc[2 * ks][2],     acc[2 * ks][3],     ah[1], al[1]);
            split2(acc[2 * ks + 1][0], acc[2 * ks + 1][1], ah[2], al[2]);
            split2(acc[2 * ks + 1][2], acc[2 * ks + 1][3], ah[3], al[3]);
            uint32_t rbase = vrow_h + ks * 2304;
#pragma unroll
            for (int g = 0; g < 2; g++) {
                uint32_t bh[4][2], bl[4][2];
#pragma unroll
                for (int jj = 0; jj < 4; jj++) {
                    ldmat_x2_trans(bh[jj][0], bh[jj][1], rbase + (g * 4 + jj) * 16);
                    ldmat_x2_trans(bl[jj][0], bl[jj][1], rbase + (g * 4 + jj) * 16 + 9216);
                }
#pragma unroll
                for (int jj = 0; jj < 4; jj++) mma_bf16(accO[g * 4 + jj], ah, bh[jj]);
#pragma unroll
                for (int jj = 0; jj < 4; jj++) mma_bf16(accO[g * 4 + jj], al, bh[jj]);
#pragma unroll
                for (int jj = 0; jj < 4; jj++) mma_bf16(accO[g * 4 + jj], ah, bl[jj]);
            }
        }
        __syncthreads();
    }
#undef KVFILL

    float inv0 = 1.0f / l0r, inv1 = 1.0f / l1r;
    size_t row0 = (size_t)bb * T_ + m0 + warp * 16 + grp;
    size_t row1 = row0 + 8;
#pragma unroll
    for (int jd = 0; jd < 8; jd++) {
        int w = h * 32 + jd * 4 + tig;
        uint32_t hw, lw;
        split2(accO[jd][0] * inv0, accO[jd][1] * inv0, hw, lw);
        ao_hi[row0 * 512 + w] = hw;
        ao_lo[row0 * 512 + w] = lw;
        split2(accO[jd][2] * inv1, accO[jd][3] * inv1, hw, lw);
        ao_hi[row1 * 512 + w] = hw;
        ao_lo[row1 * 512 + w] = lw;
    }
}

extern "C" void kernel_launch(void* const* d_in, const int* in_sizes, int n_in,
                              void* d_out, int out_size)
{
    const float* query = (const float*)d_in[0];
    const float* key   = (const float*)d_in[1];
    const float* value = (const float*)d_in[2];
    const unsigned char* mask = (const unsigned char*)d_in[3];
    const float* q_w = (const float*)d_in[4];
    const float* q_b = (const float*)d_in[5];
    const float* k_w = (const float*)d_in[6];
    const float* k_b = (const float*)d_in[7];
    const float* v_w = (const float*)d_in[8];
    const float* v_b = (const float*)d_in[9];
    const float* o_w = (const float*)d_in[10];
    const float* o_b = (const float*)d_in[11];
    const float* rel = (const float*)d_in[12];
    float* out = (float*)d_out;

    const int GSMEM = 81920;
    const int FSMEM = 110592;
    cudaFuncSetAttribute(proj_qkv, cudaFuncAttributeMaxDynamicSharedMemorySize, GSMEM);
    cudaFuncSetAttribute(proj_o,   cudaFuncAttributeMaxDynamicSharedMemorySize, GSMEM);
    cudaFuncSetAttribute(flash_attn, cudaFuncAttributeMaxDynamicSharedMemorySize, FSMEM);

    const int nTot = 3 * NA4 + 4 * NW4;
    split_all<<<nTot / 1024, 256>>>((const float4*)query, (const float4*)key,
                                    (const float4*)value, (const float4*)q_w,
                                    (const float4*)k_w,   (const float4*)v_w,
                                    (const float4*)o_w);

    dim3 pg(E_ / 128, (B_ * T_) / 128, 3);
    proj_qkv<<<pg, 256, GSMEM>>>(q_b, k_b, v_b, rel);

    dim3 fg(T_ / 128, B_ * H_, 1);
    flash_attn<<<fg, 256, FSMEM>>>(mask);

    dim3 og(E_ / 128, (B_ * T_) / 128, 1);
    proj_o<<<og, 256, GSMEM>>>(o_b, out);
}